// round 1
// baseline (speedup 1.0000x reference)
#include <cuda_runtime.h>
#include <cuda_bf16.h>
#include <math.h>

// Problem dims (fixed)
#define B_  4
#define T_  2048
#define D_  1024
#define H_  16
#define DH_ 64

// Scratch: qkv projections (B*T*3D) and attention output (B*T*D)
__device__ float g_qkv[(size_t)B_ * T_ * 3 * D_];   // 96 MB
__device__ float g_att[(size_t)B_ * T_ * D_];       // 32 MB

// ---------------------------------------------------------------------------
// Tiled SGEMM with bias: C[M,N] = A[M,K] @ W[K,N] + bias[N]
// 128x128 tile, BK=16, 256 threads, 8x8 per-thread microtile.
// ---------------------------------------------------------------------------
__global__ __launch_bounds__(256, 2)
void sgemm_bias_kernel(const float* __restrict__ A,
                       const float* __restrict__ W,
                       const float* __restrict__ bias,
                       float* __restrict__ C,
                       int M, int N, int K)
{
    __shared__ float As[16][128];   // transposed A tile: As[k][m]
    __shared__ float Bs[16][128];   // natural B tile:  Bs[k][n]

    const int tid = threadIdx.x;
    const int bn = blockIdx.x;      // N tile
    const int bm = blockIdx.y;      // M tile
    const int tx = tid & 15;        // 0..15 -> n micro
    const int ty = tid >> 4;        // 0..15 -> m micro

    const float* Ab = A + (size_t)bm * 128 * K;
    const float* Bb = W + (size_t)bn * 128;

    // load indices
    const int ar  = tid >> 2;          // 0..63  (A row, two passes +64)
    const int ac  = (tid & 3) << 2;    // 0,4,8,12 (A col within BK)
    const int br  = tid >> 5;          // 0..7   (B row, two passes +8)
    const int bc  = (tid & 31) << 2;   // 0..124 (B col)

    float c[8][8];
#pragma unroll
    for (int i = 0; i < 8; i++)
#pragma unroll
        for (int j = 0; j < 8; j++) c[i][j] = 0.f;

    for (int k0 = 0; k0 < K; k0 += 16) {
#pragma unroll
        for (int p = 0; p < 2; p++) {
            int r = ar + p * 64;
            float4 a4 = *(const float4*)(Ab + (size_t)r * K + k0 + ac);
            As[ac + 0][r] = a4.x;
            As[ac + 1][r] = a4.y;
            As[ac + 2][r] = a4.z;
            As[ac + 3][r] = a4.w;
            int rb = br + p * 8;
            *(float4*)&Bs[rb][bc] =
                *(const float4*)(Bb + (size_t)(k0 + rb) * N + bc);
        }
        __syncthreads();

#pragma unroll
        for (int kk = 0; kk < 16; kk++) {
            float4 a0 = *(float4*)&As[kk][ty * 8];
            float4 a1 = *(float4*)&As[kk][ty * 8 + 4];
            float4 b0 = *(float4*)&Bs[kk][tx * 8];
            float4 b1 = *(float4*)&Bs[kk][tx * 8 + 4];
            float av[8] = {a0.x, a0.y, a0.z, a0.w, a1.x, a1.y, a1.z, a1.w};
            float bv[8] = {b0.x, b0.y, b0.z, b0.w, b1.x, b1.y, b1.z, b1.w};
#pragma unroll
            for (int i = 0; i < 8; i++)
#pragma unroll
                for (int j = 0; j < 8; j++)
                    c[i][j] += av[i] * bv[j];
        }
        __syncthreads();
    }

    // epilogue: bias add + store
    const int ncol = bn * 128 + tx * 8;
    float4 bi0 = *(const float4*)(bias + ncol);
    float4 bi1 = *(const float4*)(bias + ncol + 4);
#pragma unroll
    for (int i = 0; i < 8; i++) {
        size_t row = (size_t)bm * 128 + ty * 8 + i;
        float4 w0 = make_float4(c[i][0] + bi0.x, c[i][1] + bi0.y,
                                c[i][2] + bi0.z, c[i][3] + bi0.w);
        float4 w1 = make_float4(c[i][4] + bi1.x, c[i][5] + bi1.y,
                                c[i][6] + bi1.z, c[i][7] + bi1.w);
        *(float4*)(C + row * N + ncol)     = w0;
        *(float4*)(C + row * N + ncol + 4) = w1;
    }
}

// ---------------------------------------------------------------------------
// Flash attention: per (b,h), 64-query x 64-key tiles, online softmax.
// scores = QK^T/8; mask==0 -> -1000 (exact, matching reference); softmax; @V.
// blockDim = 256 (16x16 threads, each owning a 4x4 microtile).
// ---------------------------------------------------------------------------
__global__ __launch_bounds__(256, 2)
void attn_kernel(const float* __restrict__ qkv,
                 const int* __restrict__ mask,
                 float* __restrict__ out)
{
    extern __shared__ float sm[];
    float* Qs = sm;               // [64][68], transposed: Qs[d*68 + r]
    float* Ks = Qs + 64 * 68;     // [64][68], transposed: Ks[d*68 + c]
    float* Vs = Ks + 64 * 68;     // [64][68], natural:    Vs[k*68 + d]
    float* Pt = Vs + 64 * 68;     // [64][68], transposed: Pt[k*68 + r]
    int* msk = (int*)(Pt + 64 * 68);  // [64]

    const int qb = blockIdx.x;          // q tile (32)
    const int bh = blockIdx.y;          // b*H + h (64)
    const int b  = bh >> 4;
    const int h  = bh & 15;
    const int tid = threadIdx.x;
    const int tx = tid & 15;
    const int ty = tid >> 4;
    const int r0 = ty * 4;              // query rows
    const int c0 = tx * 4;              // key cols / dh cols

    const size_t rs = 3 * D_;           // 3072 row stride of qkv
    const float* qbase = qkv + ((size_t)b * T_ + qb * 64) * rs + h * DH_;
    const float* kbase = qkv + (size_t)b * T_ * rs + D_ + h * DH_;
    const int*   mbase = mask + (size_t)b * T_;

    // load Q tile, transposed
    {
        const int lr = tid >> 4;             // 0..15
        const int lc = (tid & 15) << 2;      // 0..60
#pragma unroll
        for (int i = 0; i < 4; i++) {
            int row = lr + i * 16;
            float4 q4 = *(const float4*)(qbase + (size_t)row * rs + lc);
            Qs[(lc + 0) * 68 + row] = q4.x;
            Qs[(lc + 1) * 68 + row] = q4.y;
            Qs[(lc + 2) * 68 + row] = q4.z;
            Qs[(lc + 3) * 68 + row] = q4.w;
        }
    }

    float o[4][4];
    float mrow[4], lrow[4];
#pragma unroll
    for (int i = 0; i < 4; i++) {
        mrow[i] = -3.0e38f;
        lrow[i] = 0.f;
#pragma unroll
        for (int j = 0; j < 4; j++) o[i][j] = 0.f;
    }

    for (int kb = 0; kb < T_ / 64; kb++) {
        __syncthreads();   // previous iteration done reading Vs/Pt
        {
            const int lr = tid >> 4;
            const int lc = (tid & 15) << 2;
#pragma unroll
            for (int i = 0; i < 4; i++) {
                int row = lr + i * 16;
                const float* kp = kbase + (size_t)(kb * 64 + row) * rs + lc;
                float4 k4 = *(const float4*)kp;
                float4 v4 = *(const float4*)(kp + D_);   // V is +D after K
                Ks[(lc + 0) * 68 + row] = k4.x;
                Ks[(lc + 1) * 68 + row] = k4.y;
                Ks[(lc + 2) * 68 + row] = k4.z;
                Ks[(lc + 3) * 68 + row] = k4.w;
                *(float4*)&Vs[row * 68 + lc] = v4;
            }
            if (tid < 64) msk[tid] = mbase[kb * 64 + tid];
        }
        __syncthreads();

        // S = Q K^T  (64x64x64)
        float s[4][4];
#pragma unroll
        for (int i = 0; i < 4; i++)
#pragma unroll
            for (int j = 0; j < 4; j++) s[i][j] = 0.f;

#pragma unroll 16
        for (int d = 0; d < 64; d++) {
            float4 a  = *(float4*)&Qs[d * 68 + r0];
            float4 bb = *(float4*)&Ks[d * 68 + c0];
            s[0][0] += a.x * bb.x; s[0][1] += a.x * bb.y;
            s[0][2] += a.x * bb.z; s[0][3] += a.x * bb.w;
            s[1][0] += a.y * bb.x; s[1][1] += a.y * bb.y;
            s[1][2] += a.y * bb.z; s[1][3] += a.y * bb.w;
            s[2][0] += a.z * bb.x; s[2][1] += a.z * bb.y;
            s[2][2] += a.z * bb.z; s[2][3] += a.z * bb.w;
            s[3][0] += a.w * bb.x; s[3][1] += a.w * bb.y;
            s[3][2] += a.w * bb.z; s[3][3] += a.w * bb.w;
        }

        // scale + mask (mask==0 -> exactly -1000, matching reference)
#pragma unroll
        for (int j = 0; j < 4; j++) {
            bool keep = (msk[c0 + j] != 0);
#pragma unroll
            for (int i = 0; i < 4; i++)
                s[i][j] = keep ? s[i][j] * 0.125f : -1000.0f;
        }

        // online softmax (rows reduced across the 16-lane tx group)
#pragma unroll
        for (int i = 0; i < 4; i++) {
            float mx = fmaxf(fmaxf(s[i][0], s[i][1]), fmaxf(s[i][2], s[i][3]));
#pragma unroll
            for (int off = 8; off; off >>= 1)
                mx = fmaxf(mx, __shfl_xor_sync(0xffffffffu, mx, off, 16));
            float mn = fmaxf(mrow[i], mx);
            float corr = __expf(mrow[i] - mn);
            mrow[i] = mn;
            float ps = 0.f;
#pragma unroll
            for (int j = 0; j < 4; j++) {
                float p = __expf(s[i][j] - mn);
                s[i][j] = p;
                ps += p;
            }
#pragma unroll
            for (int off = 8; off; off >>= 1)
                ps += __shfl_xor_sync(0xffffffffu, ps, off, 16);
            lrow[i] = lrow[i] * corr + ps;
#pragma unroll
            for (int j = 0; j < 4; j++) o[i][j] *= corr;
        }

        // stage P transposed for the PV GEMM
#pragma unroll
        for (int j = 0; j < 4; j++)
#pragma unroll
            for (int i = 0; i < 4; i++)
                Pt[(c0 + j) * 68 + r0 + i] = s[i][j];
        __syncthreads();

        // O += P @ V  (64x64x64)
#pragma unroll 16
        for (int k = 0; k < 64; k++) {
            float4 a  = *(float4*)&Pt[k * 68 + r0];
            float4 bb = *(float4*)&Vs[k * 68 + c0];
            o[0][0] += a.x * bb.x; o[0][1] += a.x * bb.y;
            o[0][2] += a.x * bb.z; o[0][3] += a.x * bb.w;
            o[1][0] += a.y * bb.x; o[1][1] += a.y * bb.y;
            o[1][2] += a.y * bb.z; o[1][3] += a.y * bb.w;
            o[2][0] += a.z * bb.x; o[2][1] += a.z * bb.y;
            o[2][2] += a.z * bb.z; o[2][3] += a.z * bb.w;
            o[3][0] += a.w * bb.x; o[3][1] += a.w * bb.y;
            o[3][2] += a.w * bb.z; o[3][3] += a.w * bb.w;
        }
    }

    // normalize + store to g_att[(b*T + q)*D + h*64 + d]
    float* ob = out + ((size_t)b * T_ + qb * 64) * D_ + h * DH_;
#pragma unroll
    for (int i = 0; i < 4; i++) {
        float inv = 1.0f / lrow[i];
        float4 w = make_float4(o[i][0] * inv, o[i][1] * inv,
                               o[i][2] * inv, o[i][3] * inv);
        *(float4*)(ob + (size_t)(r0 + i) * D_ + c0) = w;
    }
}

// ---------------------------------------------------------------------------
// launch
// ---------------------------------------------------------------------------
extern "C" void kernel_launch(void* const* d_in, const int* in_sizes, int n_in,
                              void* d_out, int out_size)
{
    const float* x     = (const float*)d_in[0];   // [B,T,D]
    const int*   mask  = (const int*)  d_in[1];   // [B,1,1,T]
    const float* W_qkv = (const float*)d_in[2];   // [D,3D]
    const float* b_qkv = (const float*)d_in[3];   // [3D]
    const float* W_out = (const float*)d_in[4];   // [D,D]
    const float* b_out = (const float*)d_in[5];   // [D]
    float* out = (float*)d_out;                   // [B,T,D]

    void* p;
    cudaGetSymbolAddress(&p, g_qkv);
    float* qkv = (float*)p;
    cudaGetSymbolAddress(&p, g_att);
    float* att = (float*)p;

    const int M = B_ * T_;          // 8192

    // 1) QKV projection: [8192,1024] @ [1024,3072] + b
    {
        dim3 grid(3 * D_ / 128, M / 128);
        sgemm_bias_kernel<<<grid, 256>>>(x, W_qkv, b_qkv, qkv, M, 3 * D_, D_);
    }

    // 2) attention
    {
        const int smem = (4 * 64 * 68) * (int)sizeof(float) + 64 * (int)sizeof(int);
        cudaFuncSetAttribute(attn_kernel,
                             cudaFuncAttributeMaxDynamicSharedMemorySize, smem);
        dim3 grid(T_ / 64, B_ * H_);
        attn_kernel<<<grid, 256, smem>>>(qkv, mask, att);
    }

    // 3) output projection: [8192,1024] @ [1024,1024] + b
    {
        dim3 grid(D_ / 128, M / 128);
        sgemm_bias_kernel<<<grid, 256>>>(att, W_out, b_out, out, M, D_, D_);
    }
}

// round 3
// speedup vs baseline: 3.0973x; 3.0973x over previous
#include <cuda_runtime.h>
#include <math.h>
#include <cstdint>

// Problem dims (fixed)
#define B_  4
#define T_  2048
#define D_  1024
#define H_  16
#define DH_ 64

// Scratch
__device__ float g_qkv[(size_t)B_ * T_ * 3 * D_];   // 96 MB
__device__ float g_att[(size_t)B_ * T_ * D_];       // 32 MB

// ---------------------------------------------------------------------------
// helpers
// ---------------------------------------------------------------------------
__device__ __forceinline__ uint32_t f2tf(float f) {
    uint32_t r;
    asm("cvt.rna.tf32.f32 %0, %1;" : "=r"(r) : "f"(f));
    return r;
}

__device__ __forceinline__ void mma8(float* d, const uint32_t* a,
                                     uint32_t b0, uint32_t b1) {
    asm volatile(
        "mma.sync.aligned.m16n8k8.row.col.f32.tf32.tf32.f32 "
        "{%0,%1,%2,%3}, {%4,%5,%6,%7}, {%8,%9}, {%0,%1,%2,%3};"
        : "+f"(d[0]), "+f"(d[1]), "+f"(d[2]), "+f"(d[3])
        : "r"(a[0]), "r"(a[1]), "r"(a[2]), "r"(a[3]), "r"(b0), "r"(b1));
}

__device__ __forceinline__ void cp16(uint32_t dst, const void* src) {
    asm volatile("cp.async.cg.shared.global [%0], [%1], 16;" :: "r"(dst), "l"(src));
}
__device__ __forceinline__ uint32_t smem_u32(const void* p) {
    uint32_t a;
    asm("{ .reg .u64 t; cvta.to.shared.u64 t, %1; cvt.u32.u64 %0, t; }"
        : "=r"(a) : "l"(p));
    return a;
}

// ---------------------------------------------------------------------------
// Projection GEMM via mma.sync tf32:
//   C[M,N] = A[M,K] @ W[K,N] + bias[N]
// 128x128 block tile, BK=32, 8 warps (2x4), warp tile 64x32.
// 4-stage cp.async pipeline. A smem stride 36, B smem stride 136 (bank-safe).
// ---------------------------------------------------------------------------
#define GA_STRIDE 36
#define GB_STRIDE 136
#define STAGE_FLOATS (128 * GA_STRIDE + 32 * GB_STRIDE)   // 8960
#define GSTAGES 4
#define GSMEM_BYTES (GSTAGES * STAGE_FLOATS * 4)          // 143360

__global__ __launch_bounds__(256, 1)
void gemm_mma_kernel(const float* __restrict__ A, const float* __restrict__ W,
                     const float* __restrict__ bias, float* __restrict__ C,
                     int M, int N, int K)
{
    extern __shared__ float smf[];
    const uint32_t sb = smem_u32(smf);
    const int tid = threadIdx.x;
    const int w = tid >> 5, lane = tid & 31;
    const int g = lane >> 2, t = lane & 3;
    const int bn = blockIdx.x, bm = blockIdx.y;
    const int m0 = (w >> 2) * 64, n0 = (w & 3) * 32;

    const float* Ag = A + (size_t)bm * 128 * K;
    const float* Wg = W + bn * 128;

    float acc[4][4][4];
#pragma unroll
    for (int mi = 0; mi < 4; mi++)
#pragma unroll
        for (int ni = 0; ni < 4; ni++)
#pragma unroll
            for (int j = 0; j < 4; j++) acc[mi][ni][j] = 0.f;

#define G_LOAD(ch, s) do {                                                     \
        uint32_t abase = sb + (uint32_t)(s) * (STAGE_FLOATS * 4);              \
        uint32_t bbase = abase + 128 * GA_STRIDE * 4;                          \
        int k0 = (ch) * 32;                                                    \
        _Pragma("unroll")                                                      \
        for (int i = 0; i < 4; i++) {                                          \
            int idx = tid + i * 256;                                           \
            int ar = idx >> 3, ac = (idx & 7) * 4;                             \
            cp16(abase + (uint32_t)(ar * GA_STRIDE + ac) * 4,                  \
                 Ag + (size_t)ar * K + k0 + ac);                               \
            int br = idx >> 5, bc = (idx & 31) * 4;                            \
            cp16(bbase + (uint32_t)(br * GB_STRIDE + bc) * 4,                  \
                 Wg + (size_t)(k0 + br) * N + bc);                             \
        }                                                                      \
    } while (0)

    const int NC = K / 32;
#pragma unroll
    for (int c = 0; c < GSTAGES; c++) {
        G_LOAD(c, c);
        asm volatile("cp.async.commit_group;" ::: "memory");
    }

    for (int c = 0; c < NC; c++) {
        int s = c & (GSTAGES - 1);
        asm volatile("cp.async.wait_group 3;" ::: "memory");
        __syncthreads();
        const float* As = smf + (size_t)s * STAGE_FLOATS;
        const float* Bs = As + 128 * GA_STRIDE;

#pragma unroll
        for (int ks = 0; ks < 4; ks++) {
            uint32_t af[4][4];
#pragma unroll
            for (int mi = 0; mi < 4; mi++) {
                int row = m0 + mi * 16 + g;
                af[mi][0] = f2tf(As[row * GA_STRIDE + ks * 8 + t]);
                af[mi][1] = f2tf(As[(row + 8) * GA_STRIDE + ks * 8 + t]);
                af[mi][2] = f2tf(As[row * GA_STRIDE + ks * 8 + t + 4]);
                af[mi][3] = f2tf(As[(row + 8) * GA_STRIDE + ks * 8 + t + 4]);
            }
#pragma unroll
            for (int ni = 0; ni < 4; ni++) {
                uint32_t b0 = f2tf(Bs[(ks * 8 + t) * GB_STRIDE + n0 + ni * 8 + g]);
                uint32_t b1 = f2tf(Bs[(ks * 8 + t + 4) * GB_STRIDE + n0 + ni * 8 + g]);
#pragma unroll
                for (int mi = 0; mi < 4; mi++)
                    mma8(acc[mi][ni], af[mi], b0, b1);
            }
        }
        __syncthreads();
        if (c + GSTAGES < NC) G_LOAD(c + GSTAGES, s);
        asm volatile("cp.async.commit_group;" ::: "memory");
    }

    // epilogue: bias + store (float2 per fragment row)
#pragma unroll
    for (int mi = 0; mi < 4; mi++) {
        int rA = bm * 128 + m0 + mi * 16 + g;
        int rB = rA + 8;
#pragma unroll
        for (int ni = 0; ni < 4; ni++) {
            int col = bn * 128 + n0 + ni * 8 + t * 2;
            float bx = bias[col], by = bias[col + 1];
            *(float2*)(C + (size_t)rA * N + col) =
                make_float2(acc[mi][ni][0] + bx, acc[mi][ni][1] + by);
            *(float2*)(C + (size_t)rB * N + col) =
                make_float2(acc[mi][ni][2] + bx, acc[mi][ni][3] + by);
        }
    }
}

// ---------------------------------------------------------------------------
// Flash attention via mma.sync tf32.
// Block: 128 q-rows x 64 dh, 8 warps (16 q-rows each). Loop over 32 k-tiles
// of 64 keys. Q fragments live in registers (pre-scaled by 0.125, tf32).
// K/V tf32-rounded at smem fill. P staged per-warp (warp-private rows).
// ---------------------------------------------------------------------------
#define KS_STRIDE 68
#define VS_STRIDE 72
#define PT_STRIDE 68
// floats: Ks 64*68=4352 | Vs 64*72=4608 | Pt 128*68=8704 | msk 64 ints
#define ATT_KS_OFF 0
#define ATT_VS_OFF 4352
#define ATT_PT_OFF 8960
#define ATT_MSK_OFF 17664
#define ATT_SMEM_BYTES ((17664 + 64) * 4)    // 70912

__global__ __launch_bounds__(256, 2)
void attn_mma_kernel(const float* __restrict__ qkv,
                     const int* __restrict__ mask,
                     float* __restrict__ out)
{
    extern __shared__ float smf[];
    float* Ks = smf + ATT_KS_OFF;
    float* Vs = smf + ATT_VS_OFF;
    float* Pt = smf + ATT_PT_OFF;
    int*   msk = (int*)(smf + ATT_MSK_OFF);
    const uint32_t* Ksu = (const uint32_t*)Ks;
    const uint32_t* Vsu = (const uint32_t*)Vs;
    const uint32_t* Ptu = (const uint32_t*)Pt;

    const int qb = blockIdx.x;          // 16 tiles of 128 q rows
    const int bh = blockIdx.y;          // 64
    const int b  = bh >> 4;
    const int h  = bh & 15;
    const int tid = threadIdx.x;
    const int w = tid >> 5, lane = tid & 31;
    const int g = lane >> 2, t = lane & 3;
    const int w16 = w * 16;

    const size_t rs = 3 * D_;
    const float* qbase = qkv + ((size_t)b * T_ + qb * 128) * rs + h * DH_;
    const float* kbase = qkv + (size_t)b * T_ * rs + D_ + h * DH_;
    const int*   mbase = mask + (size_t)b * T_;

    // ---- stage Q (scaled + tf32) into Pt area, then load fragments ----
#pragma unroll
    for (int i = 0; i < 8; i++) {
        int idx = tid + i * 256;
        int row = idx >> 4, fc = (idx & 15) * 4;
        float4 q4 = *(const float4*)(qbase + (size_t)row * rs + fc);
        float4 sq;
        sq.x = __uint_as_float(f2tf(q4.x * 0.125f));
        sq.y = __uint_as_float(f2tf(q4.y * 0.125f));
        sq.z = __uint_as_float(f2tf(q4.z * 0.125f));
        sq.w = __uint_as_float(f2tf(q4.w * 0.125f));
        *(float4*)(Pt + row * PT_STRIDE + fc) = sq;
    }
    __syncthreads();

    uint32_t qf[8][4];
#pragma unroll
    for (int ks = 0; ks < 8; ks++) {
        int row = w16 + g;
        qf[ks][0] = Ptu[row * PT_STRIDE + ks * 8 + t];
        qf[ks][1] = Ptu[(row + 8) * PT_STRIDE + ks * 8 + t];
        qf[ks][2] = Ptu[row * PT_STRIDE + ks * 8 + t + 4];
        qf[ks][3] = Ptu[(row + 8) * PT_STRIDE + ks * 8 + t + 4];
    }

    float of[8][4];
#pragma unroll
    for (int n = 0; n < 8; n++)
#pragma unroll
        for (int j = 0; j < 4; j++) of[n][j] = 0.f;
    float mrA = -3.0e38f, mrB = -3.0e38f, lrA = 0.f, lrB = 0.f;

    for (int kb = 0; kb < T_ / 64; kb++) {
        __syncthreads();   // everyone done with previous Ks/Vs/Pt
        // fill K/V (tf32-rounded) + mask
#pragma unroll
        for (int i = 0; i < 4; i++) {
            int idx = tid + i * 256;
            int row = idx >> 4, fc = (idx & 15) * 4;
            const float* kp = kbase + (size_t)(kb * 64 + row) * rs + fc;
            float4 k4 = *(const float4*)kp;
            float4 v4 = *(const float4*)(kp + D_);
            float4 kc, vc;
            kc.x = __uint_as_float(f2tf(k4.x)); kc.y = __uint_as_float(f2tf(k4.y));
            kc.z = __uint_as_float(f2tf(k4.z)); kc.w = __uint_as_float(f2tf(k4.w));
            vc.x = __uint_as_float(f2tf(v4.x)); vc.y = __uint_as_float(f2tf(v4.y));
            vc.z = __uint_as_float(f2tf(v4.z)); vc.w = __uint_as_float(f2tf(v4.w));
            *(float4*)(Ks + row * KS_STRIDE + fc) = kc;
            *(float4*)(Vs + row * VS_STRIDE + fc) = vc;
        }
        if (tid < 64) msk[tid] = mbase[kb * 64 + tid];
        __syncthreads();

        // ---- S = Q K^T  (per warp: 16x64, 8 n-atoms x 8 k-steps) ----
        float sf[8][4];
#pragma unroll
        for (int n = 0; n < 8; n++)
#pragma unroll
            for (int j = 0; j < 4; j++) sf[n][j] = 0.f;

#pragma unroll
        for (int ks = 0; ks < 8; ks++) {
#pragma unroll
            for (int n = 0; n < 8; n++) {
                uint32_t b0 = Ksu[(n * 8 + g) * KS_STRIDE + ks * 8 + t];
                uint32_t b1 = Ksu[(n * 8 + g) * KS_STRIDE + ks * 8 + t + 4];
                mma8(sf[n], qf[ks], b0, b1);
            }
        }

        // ---- mask + online softmax (rows g and g+8) ----
#pragma unroll
        for (int n = 0; n < 8; n++) {
            int c0 = n * 8 + t * 2;
            bool k0 = msk[c0] != 0, k1 = msk[c0 + 1] != 0;
            sf[n][0] = k0 ? sf[n][0] : -1000.0f;
            sf[n][1] = k1 ? sf[n][1] : -1000.0f;
            sf[n][2] = k0 ? sf[n][2] : -1000.0f;
            sf[n][3] = k1 ? sf[n][3] : -1000.0f;
        }
        float mA = -3.0e38f, mB = -3.0e38f;
#pragma unroll
        for (int n = 0; n < 8; n++) {
            mA = fmaxf(mA, fmaxf(sf[n][0], sf[n][1]));
            mB = fmaxf(mB, fmaxf(sf[n][2], sf[n][3]));
        }
        mA = fmaxf(mA, __shfl_xor_sync(0xffffffffu, mA, 1));
        mA = fmaxf(mA, __shfl_xor_sync(0xffffffffu, mA, 2));
        mB = fmaxf(mB, __shfl_xor_sync(0xffffffffu, mB, 1));
        mB = fmaxf(mB, __shfl_xor_sync(0xffffffffu, mB, 2));

        float mnA = fmaxf(mrA, mA), mnB = fmaxf(mrB, mB);
        float corrA = __expf(mrA - mnA), corrB = __expf(mrB - mnB);
        mrA = mnA; mrB = mnB;

        float psA = 0.f, psB = 0.f;
#pragma unroll
        for (int n = 0; n < 8; n++) {
            float p0 = __expf(sf[n][0] - mnA);
            float p1 = __expf(sf[n][1] - mnA);
            float p2 = __expf(sf[n][2] - mnB);
            float p3 = __expf(sf[n][3] - mnB);
            psA += p0 + p1; psB += p2 + p3;
            int col = n * 8 + t * 2;
            *(float2*)(Pt + (w16 + g) * PT_STRIDE + col) =
                make_float2(__uint_as_float(f2tf(p0)), __uint_as_float(f2tf(p1)));
            *(float2*)(Pt + (w16 + g + 8) * PT_STRIDE + col) =
                make_float2(__uint_as_float(f2tf(p2)), __uint_as_float(f2tf(p3)));
        }
        psA += __shfl_xor_sync(0xffffffffu, psA, 1);
        psA += __shfl_xor_sync(0xffffffffu, psA, 2);
        psB += __shfl_xor_sync(0xffffffffu, psB, 1);
        psB += __shfl_xor_sync(0xffffffffu, psB, 2);
        lrA = lrA * corrA + psA;
        lrB = lrB * corrB + psB;

#pragma unroll
        for (int n = 0; n < 8; n++) {
            of[n][0] *= corrA; of[n][1] *= corrA;
            of[n][2] *= corrB; of[n][3] *= corrB;
        }
        __syncwarp();   // warp-private Pt rows written before reading

        // ---- O += P V  (8 k-steps x 8 n-atoms) ----
#pragma unroll
        for (int ks = 0; ks < 8; ks++) {
            uint32_t pa[4];
            pa[0] = Ptu[(w16 + g) * PT_STRIDE + ks * 8 + t];
            pa[1] = Ptu[(w16 + g + 8) * PT_STRIDE + ks * 8 + t];
            pa[2] = Ptu[(w16 + g) * PT_STRIDE + ks * 8 + t + 4];
            pa[3] = Ptu[(w16 + g + 8) * PT_STRIDE + ks * 8 + t + 4];
#pragma unroll
            for (int n = 0; n < 8; n++) {
                uint32_t b0 = Vsu[(ks * 8 + t) * VS_STRIDE + n * 8 + g];
                uint32_t b1 = Vsu[(ks * 8 + t + 4) * VS_STRIDE + n * 8 + g];
                mma8(of[n], pa, b0, b1);
            }
        }
    }

    // ---- normalize + store ----
    float invA = 1.0f / lrA, invB = 1.0f / lrB;
    float* ob = out + ((size_t)b * T_ + qb * 128) * D_ + h * DH_;
#pragma unroll
    for (int n = 0; n < 8; n++) {
        int col = n * 8 + t * 2;
        *(float2*)(ob + (size_t)(w16 + g) * D_ + col) =
            make_float2(of[n][0] * invA, of[n][1] * invA);
        *(float2*)(ob + (size_t)(w16 + g + 8) * D_ + col) =
            make_float2(of[n][2] * invB, of[n][3] * invB);
    }
}

// ---------------------------------------------------------------------------
// launch
// ---------------------------------------------------------------------------
extern "C" void kernel_launch(void* const* d_in, const int* in_sizes, int n_in,
                              void* d_out, int out_size)
{
    const float* x     = (const float*)d_in[0];
    const int*   mask  = (const int*)  d_in[1];
    const float* W_qkv = (const float*)d_in[2];
    const float* b_qkv = (const float*)d_in[3];
    const float* W_out = (const float*)d_in[4];
    const float* b_out = (const float*)d_in[5];
    float* out = (float*)d_out;

    void* p;
    cudaGetSymbolAddress(&p, g_qkv);   float* qkv = (float*)p;
    cudaGetSymbolAddress(&p, g_att);   float* att = (float*)p;

    const int M = B_ * T_;   // 8192

    cudaFuncSetAttribute(gemm_mma_kernel,
                         cudaFuncAttributeMaxDynamicSharedMemorySize, GSMEM_BYTES);
    cudaFuncSetAttribute(attn_mma_kernel,
                         cudaFuncAttributeMaxDynamicSharedMemorySize, ATT_SMEM_BYTES);

    // 1) QKV projection
    {
        dim3 grid(3 * D_ / 128, M / 128);
        gemm_mma_kernel<<<grid, 256, GSMEM_BYTES>>>(x, W_qkv, b_qkv, qkv,
                                                    M, 3 * D_, D_);
    }
    // 2) attention
    {
        dim3 grid(T_ / 128, B_ * H_);
        attn_mma_kernel<<<grid, 256, ATT_SMEM_BYTES>>>(qkv, mask, att);
    }
    // 3) output projection
    {
        dim3 grid(D_ / 128, M / 128);
        gemm_mma_kernel<<<grid, 256, GSMEM_BYTES>>>(att, W_out, b_out, out,
                                                    M, D_, D_);
    }
}

// round 4
// speedup vs baseline: 3.7101x; 1.1978x over previous
#include <cuda_runtime.h>
#include <math.h>
#include <cstdint>

// Problem dims (fixed)
#define B_  4
#define T_  2048
#define D_  1024
#define H_  16
#define DH_ 64

// Scratch
__device__ float g_qkv[(size_t)B_ * T_ * 3 * D_];   // 96 MB (tf32-rounded)
__device__ float g_att[(size_t)B_ * T_ * D_];       // 32 MB (tf32-rounded)
__device__ float g_xr [(size_t)B_ * T_ * D_];       // 32 MB (x rounded)
__device__ float g_wqr[(size_t)D_ * 3 * D_];        // 12 MB (W_qkv rounded)
__device__ float g_wor[(size_t)D_ * D_];            // 4 MB  (W_out rounded)

// ---------------------------------------------------------------------------
// helpers
// ---------------------------------------------------------------------------
__device__ __forceinline__ uint32_t f2tf(float f) {
    uint32_t r;
    asm("cvt.rna.tf32.f32 %0, %1;" : "=r"(r) : "f"(f));
    return r;
}
__device__ __forceinline__ void mma8(float* d, const uint32_t* a,
                                     uint32_t b0, uint32_t b1) {
    asm volatile(
        "mma.sync.aligned.m16n8k8.row.col.f32.tf32.tf32.f32 "
        "{%0,%1,%2,%3}, {%4,%5,%6,%7}, {%8,%9}, {%0,%1,%2,%3};"
        : "+f"(d[0]), "+f"(d[1]), "+f"(d[2]), "+f"(d[3])
        : "r"(a[0]), "r"(a[1]), "r"(a[2]), "r"(a[3]), "r"(b0), "r"(b1));
}
__device__ __forceinline__ void cp16(uint32_t dst, const void* src) {
    asm volatile("cp.async.cg.shared.global [%0], [%1], 16;" :: "r"(dst), "l"(src));
}
__device__ __forceinline__ uint32_t smem_u32(const void* p) {
    uint32_t a;
    asm("{ .reg .u64 t; cvta.to.shared.u64 t, %1; cvt.u32.u64 %0, t; }"
        : "=r"(a) : "l"(p));
    return a;
}

// ---------------------------------------------------------------------------
// Elementwise tf32 rounding pass (float4 vectorized, grid-stride)
// ---------------------------------------------------------------------------
__global__ void round_tf32_kernel(const float4* __restrict__ src,
                                  float4* __restrict__ dst, int n4)
{
    int i = blockIdx.x * blockDim.x + threadIdx.x;
    int stride = gridDim.x * blockDim.x;
    for (; i < n4; i += stride) {
        float4 v = src[i];
        v.x = __uint_as_float(f2tf(v.x));
        v.y = __uint_as_float(f2tf(v.y));
        v.z = __uint_as_float(f2tf(v.z));
        v.w = __uint_as_float(f2tf(v.w));
        dst[i] = v;
    }
}

// ---------------------------------------------------------------------------
// Projection GEMM via mma.sync tf32 (inputs pre-rounded, NO cvt in loop):
//   C[M,N] = A[M,K] @ W[K,N] + bias[N]
// 128x128 block tile, BK=32, 8 warps (2x4), warp tile 64x32.
// 3-stage cp.async pipeline -> 107.5KB smem -> 2 CTAs/SM.
// ---------------------------------------------------------------------------
#define GA_STRIDE 36
#define GB_STRIDE 136
#define STAGE_FLOATS (128 * GA_STRIDE + 32 * GB_STRIDE)   // 8960
#define GSTAGES 3
#define GSMEM_BYTES (GSTAGES * STAGE_FLOATS * 4)          // 107520

template <bool ROUND_C>
__global__ __launch_bounds__(256, 2)
void gemm_mma_kernel(const float* __restrict__ A, const float* __restrict__ W,
                     const float* __restrict__ bias, float* __restrict__ C,
                     int M, int N, int K)
{
    extern __shared__ float smf[];
    const uint32_t sb = smem_u32(smf);
    const int tid = threadIdx.x;
    const int w = tid >> 5, lane = tid & 31;
    const int g = lane >> 2, t = lane & 3;
    const int bn = blockIdx.x, bm = blockIdx.y;
    const int m0 = (w >> 2) * 64, n0 = (w & 3) * 32;

    const float* Ag = A + (size_t)bm * 128 * K;
    const float* Wg = W + bn * 128;

    float acc[4][4][4];
#pragma unroll
    for (int mi = 0; mi < 4; mi++)
#pragma unroll
        for (int ni = 0; ni < 4; ni++)
#pragma unroll
            for (int j = 0; j < 4; j++) acc[mi][ni][j] = 0.f;

#define G_LOAD(ch, s) do {                                                     \
        uint32_t abase = sb + (uint32_t)(s) * (STAGE_FLOATS * 4);              \
        uint32_t bbase = abase + 128 * GA_STRIDE * 4;                          \
        int k0 = (ch) * 32;                                                    \
        _Pragma("unroll")                                                      \
        for (int i = 0; i < 4; i++) {                                          \
            int idx = tid + i * 256;                                           \
            int ar = idx >> 3, ac = (idx & 7) * 4;                             \
            cp16(abase + (uint32_t)(ar * GA_STRIDE + ac) * 4,                  \
                 Ag + (size_t)ar * K + k0 + ac);                               \
            int br = idx >> 5, bc = (idx & 31) * 4;                            \
            cp16(bbase + (uint32_t)(br * GB_STRIDE + bc) * 4,                  \
                 Wg + (size_t)(k0 + br) * N + bc);                             \
        }                                                                      \
        asm volatile("cp.async.commit_group;" ::: "memory");                   \
    } while (0)

    const int NC = K / 32;
#pragma unroll
    for (int c = 0; c < GSTAGES; c++) G_LOAD(c, c);

    for (int c = 0; c < NC; c++) {
        int s = c % GSTAGES;
        asm volatile("cp.async.wait_group 2;" ::: "memory");
        __syncthreads();
        const uint32_t* As = (const uint32_t*)(smf + (size_t)s * STAGE_FLOATS);
        const uint32_t* Bs = As + 128 * GA_STRIDE;

#pragma unroll
        for (int ks = 0; ks < 4; ks++) {
            uint32_t af[4][4];
#pragma unroll
            for (int mi = 0; mi < 4; mi++) {
                int row = m0 + mi * 16 + g;
                af[mi][0] = As[row * GA_STRIDE + ks * 8 + t];
                af[mi][1] = As[(row + 8) * GA_STRIDE + ks * 8 + t];
                af[mi][2] = As[row * GA_STRIDE + ks * 8 + t + 4];
                af[mi][3] = As[(row + 8) * GA_STRIDE + ks * 8 + t + 4];
            }
#pragma unroll
            for (int ni = 0; ni < 4; ni++) {
                uint32_t b0 = Bs[(ks * 8 + t) * GB_STRIDE + n0 + ni * 8 + g];
                uint32_t b1 = Bs[(ks * 8 + t + 4) * GB_STRIDE + n0 + ni * 8 + g];
#pragma unroll
                for (int mi = 0; mi < 4; mi++)
                    mma8(acc[mi][ni], af[mi], b0, b1);
            }
        }
        __syncthreads();
        if (c + GSTAGES < NC) {
            G_LOAD(c + GSTAGES, s);
        } else {
            asm volatile("cp.async.commit_group;" ::: "memory");
        }
    }

    // epilogue: bias + (optional tf32 round) + store
#pragma unroll
    for (int mi = 0; mi < 4; mi++) {
        int rA = bm * 128 + m0 + mi * 16 + g;
        int rB = rA + 8;
#pragma unroll
        for (int ni = 0; ni < 4; ni++) {
            int col = bn * 128 + n0 + ni * 8 + t * 2;
            float bx = bias[col], by = bias[col + 1];
            float v0 = acc[mi][ni][0] + bx, v1 = acc[mi][ni][1] + by;
            float v2 = acc[mi][ni][2] + bx, v3 = acc[mi][ni][3] + by;
            if (ROUND_C) {
                v0 = __uint_as_float(f2tf(v0)); v1 = __uint_as_float(f2tf(v1));
                v2 = __uint_as_float(f2tf(v2)); v3 = __uint_as_float(f2tf(v3));
            }
            *(float2*)(C + (size_t)rA * N + col) = make_float2(v0, v1);
            *(float2*)(C + (size_t)rB * N + col) = make_float2(v2, v3);
        }
    }
}

// ---------------------------------------------------------------------------
// Flash attention via mma.sync tf32, double-buffered cp.async K/V tiles.
// Block: 128 q-rows, 8 warps (16 q-rows each). 32 k-tiles of 64 keys.
// qkv is pre-rounded tf32 -> no cvt for Q/K/V. P staged per-warp (rounded).
// ---------------------------------------------------------------------------
#define KS_STRIDE 68
#define VS_STRIDE 72
#define PT_STRIDE 68
#define KS_OFF(s) ((s) * 4352)              // 2 x 64*68
#define VS_OFF(s) (8704 + (s) * 4608)       // 2 x 64*72
#define PT_OFF    17920                     // 128*68 = 8704
#define MSK_OFF   26624                     // 2 x 64 ints
#define ATT_FLOATS 26752
#define ATT_SMEM_BYTES (ATT_FLOATS * 4)     // 107008

__global__ __launch_bounds__(256, 2)
void attn_mma_kernel(const float* __restrict__ qkv,
                     const int* __restrict__ mask,
                     float* __restrict__ out)
{
    extern __shared__ float smf[];
    const uint32_t sb = smem_u32(smf);
    float* Pt = smf + PT_OFF;
    const uint32_t* Ptu = (const uint32_t*)Pt;

    const int qb = blockIdx.x;
    const int bh = blockIdx.y;
    const int b  = bh >> 4;
    const int h  = bh & 15;
    const int tid = threadIdx.x;
    const int w = tid >> 5, lane = tid & 31;
    const int g = lane >> 2, t = lane & 3;
    const int w16 = w * 16;

    const size_t rs = 3 * D_;
    const float* qbase = qkv + ((size_t)b * T_ + qb * 128) * rs + h * DH_;
    const float* kbase = qkv + (size_t)b * T_ * rs + D_ + h * DH_;
    const int*   mbase = mask + (size_t)b * T_;

    // K/V + mask tile load into stage s via cp.async (8 cp16 + mask)
#define ATT_LOAD(kb, s) do {                                                   \
        uint32_t kdst = sb + KS_OFF(s) * 4;                                    \
        uint32_t vdst = sb + VS_OFF(s) * 4;                                    \
        _Pragma("unroll")                                                      \
        for (int i = 0; i < 4; i++) {                                          \
            int idx = tid + i * 256;                                           \
            int row = idx >> 4, c16 = idx & 15;                                \
            const float* kp = kbase + (size_t)((kb) * 64 + row) * rs + c16 * 4;\
            cp16(kdst + (uint32_t)(row * KS_STRIDE + c16 * 4) * 4, kp);        \
            cp16(vdst + (uint32_t)(row * VS_STRIDE + c16 * 4) * 4, kp + D_);   \
        }                                                                      \
        if (tid < 16)                                                          \
            cp16(sb + (MSK_OFF + (s) * 64 + tid * 4) * 4,                      \
                 mbase + (kb) * 64 + tid * 4);                                 \
        asm volatile("cp.async.commit_group;" ::: "memory");                   \
    } while (0)

    ATT_LOAD(0, 0);   // prologue

    // stage Q (x 0.125, exact -> stays tf32) into Pt, then fragments
#pragma unroll
    for (int i = 0; i < 8; i++) {
        int idx = tid + i * 256;
        int row = idx >> 4, fc = (idx & 15) * 4;
        float4 q4 = *(const float4*)(qbase + (size_t)row * rs + fc);
        q4.x *= 0.125f; q4.y *= 0.125f; q4.z *= 0.125f; q4.w *= 0.125f;
        *(float4*)(Pt + row * PT_STRIDE + fc) = q4;
    }
    __syncthreads();

    uint32_t qf[8][4];
#pragma unroll
    for (int ks = 0; ks < 8; ks++) {
        int row = w16 + g;
        qf[ks][0] = Ptu[row * PT_STRIDE + ks * 8 + t];
        qf[ks][1] = Ptu[(row + 8) * PT_STRIDE + ks * 8 + t];
        qf[ks][2] = Ptu[row * PT_STRIDE + ks * 8 + t + 4];
        qf[ks][3] = Ptu[(row + 8) * PT_STRIDE + ks * 8 + t + 4];
    }

    float of[8][4];
#pragma unroll
    for (int n = 0; n < 8; n++)
#pragma unroll
        for (int j = 0; j < 4; j++) of[n][j] = 0.f;
    float mrA = -3.0e38f, mrB = -3.0e38f, lrA = 0.f, lrB = 0.f;

    const int NT = T_ / 64;
    for (int kb = 0; kb < NT; kb++) {
        int s = kb & 1;
        __syncthreads();    // all warps done reading stage s from 2 tiles ago
        if (kb + 1 < NT) {
            ATT_LOAD(kb + 1, s ^ 1);
        } else {
            asm volatile("cp.async.commit_group;" ::: "memory");
        }
        asm volatile("cp.async.wait_group 1;" ::: "memory");
        __syncthreads();    // stage s data visible to all warps

        const uint32_t* Ksu = (const uint32_t*)(smf + KS_OFF(s));
        const uint32_t* Vsu = (const uint32_t*)(smf + VS_OFF(s));
        const int* msk = (const int*)(smf + MSK_OFF) + s * 64;

        // ---- S = Q K^T ----
        float sf[8][4];
#pragma unroll
        for (int n = 0; n < 8; n++)
#pragma unroll
            for (int j = 0; j < 4; j++) sf[n][j] = 0.f;

#pragma unroll
        for (int ks = 0; ks < 8; ks++) {
#pragma unroll
            for (int n = 0; n < 8; n++) {
                uint32_t b0 = Ksu[(n * 8 + g) * KS_STRIDE + ks * 8 + t];
                uint32_t b1 = Ksu[(n * 8 + g) * KS_STRIDE + ks * 8 + t + 4];
                mma8(sf[n], qf[ks], b0, b1);
            }
        }

        // ---- mask + online softmax ----
#pragma unroll
        for (int n = 0; n < 8; n++) {
            int c0 = n * 8 + t * 2;
            bool k0 = msk[c0] != 0, k1 = msk[c0 + 1] != 0;
            sf[n][0] = k0 ? sf[n][0] : -1000.0f;
            sf[n][1] = k1 ? sf[n][1] : -1000.0f;
            sf[n][2] = k0 ? sf[n][2] : -1000.0f;
            sf[n][3] = k1 ? sf[n][3] : -1000.0f;
        }
        float mA = -3.0e38f, mB = -3.0e38f;
#pragma unroll
        for (int n = 0; n < 8; n++) {
            mA = fmaxf(mA, fmaxf(sf[n][0], sf[n][1]));
            mB = fmaxf(mB, fmaxf(sf[n][2], sf[n][3]));
        }
        mA = fmaxf(mA, __shfl_xor_sync(0xffffffffu, mA, 1));
        mA = fmaxf(mA, __shfl_xor_sync(0xffffffffu, mA, 2));
        mB = fmaxf(mB, __shfl_xor_sync(0xffffffffu, mB, 1));
        mB = fmaxf(mB, __shfl_xor_sync(0xffffffffu, mB, 2));

        float mnA = fmaxf(mrA, mA), mnB = fmaxf(mrB, mB);
        float corrA = __expf(mrA - mnA), corrB = __expf(mrB - mnB);
        mrA = mnA; mrB = mnB;

        float psA = 0.f, psB = 0.f;
#pragma unroll
        for (int n = 0; n < 8; n++) {
            float p0 = __expf(sf[n][0] - mnA);
            float p1 = __expf(sf[n][1] - mnA);
            float p2 = __expf(sf[n][2] - mnB);
            float p3 = __expf(sf[n][3] - mnB);
            psA += p0 + p1; psB += p2 + p3;
            int col = n * 8 + t * 2;
            *(float2*)(Pt + (w16 + g) * PT_STRIDE + col) =
                make_float2(__uint_as_float(f2tf(p0)), __uint_as_float(f2tf(p1)));
            *(float2*)(Pt + (w16 + g + 8) * PT_STRIDE + col) =
                make_float2(__uint_as_float(f2tf(p2)), __uint_as_float(f2tf(p3)));
        }
        psA += __shfl_xor_sync(0xffffffffu, psA, 1);
        psA += __shfl_xor_sync(0xffffffffu, psA, 2);
        psB += __shfl_xor_sync(0xffffffffu, psB, 1);
        psB += __shfl_xor_sync(0xffffffffu, psB, 2);
        lrA = lrA * corrA + psA;
        lrB = lrB * corrB + psB;

#pragma unroll
        for (int n = 0; n < 8; n++) {
            of[n][0] *= corrA; of[n][1] *= corrA;
            of[n][2] *= corrB; of[n][3] *= corrB;
        }
        __syncwarp();   // warp-private Pt rows written before reading

        // ---- O += P V ----
#pragma unroll
        for (int ks = 0; ks < 8; ks++) {
            uint32_t pa[4];
            pa[0] = Ptu[(w16 + g) * PT_STRIDE + ks * 8 + t];
            pa[1] = Ptu[(w16 + g + 8) * PT_STRIDE + ks * 8 + t];
            pa[2] = Ptu[(w16 + g) * PT_STRIDE + ks * 8 + t + 4];
            pa[3] = Ptu[(w16 + g + 8) * PT_STRIDE + ks * 8 + t + 4];
#pragma unroll
            for (int n = 0; n < 8; n++) {
                uint32_t b0 = Vsu[(ks * 8 + t) * VS_STRIDE + n * 8 + g];
                uint32_t b1 = Vsu[(ks * 8 + t + 4) * VS_STRIDE + n * 8 + g];
                mma8(of[n], pa, b0, b1);
            }
        }
    }

    // ---- normalize + tf32-round (feeds GEMM-2) + store ----
    float invA = 1.0f / lrA, invB = 1.0f / lrB;
    float* ob = out + ((size_t)b * T_ + qb * 128) * D_ + h * DH_;
#pragma unroll
    for (int n = 0; n < 8; n++) {
        int col = n * 8 + t * 2;
        *(float2*)(ob + (size_t)(w16 + g) * D_ + col) =
            make_float2(__uint_as_float(f2tf(of[n][0] * invA)),
                        __uint_as_float(f2tf(of[n][1] * invA)));
        *(float2*)(ob + (size_t)(w16 + g + 8) * D_ + col) =
            make_float2(__uint_as_float(f2tf(of[n][2] * invB)),
                        __uint_as_float(f2tf(of[n][3] * invB)));
    }
}

// ---------------------------------------------------------------------------
// launch
// ---------------------------------------------------------------------------
extern "C" void kernel_launch(void* const* d_in, const int* in_sizes, int n_in,
                              void* d_out, int out_size)
{
    const float* x     = (const float*)d_in[0];
    const int*   mask  = (const int*)  d_in[1];
    const float* W_qkv = (const float*)d_in[2];
    const float* b_qkv = (const float*)d_in[3];
    const float* W_out = (const float*)d_in[4];
    const float* b_out = (const float*)d_in[5];
    float* out = (float*)d_out;

    void* p;
    cudaGetSymbolAddress(&p, g_qkv); float* qkv = (float*)p;
    cudaGetSymbolAddress(&p, g_att); float* att = (float*)p;
    cudaGetSymbolAddress(&p, g_xr);  float* xr  = (float*)p;
    cudaGetSymbolAddress(&p, g_wqr); float* wqr = (float*)p;
    cudaGetSymbolAddress(&p, g_wor); float* wor = (float*)p;

    const int M = B_ * T_;   // 8192

    // 0) tf32-round inputs once
    round_tf32_kernel<<<2048, 256>>>((const float4*)x, (float4*)xr,
                                     M * D_ / 4);
    round_tf32_kernel<<<2048, 256>>>((const float4*)W_qkv, (float4*)wqr,
                                     D_ * 3 * D_ / 4);
    round_tf32_kernel<<<1024, 256>>>((const float4*)W_out, (float4*)wor,
                                     D_ * D_ / 4);

    cudaFuncSetAttribute(gemm_mma_kernel<true>,
                         cudaFuncAttributeMaxDynamicSharedMemorySize, GSMEM_BYTES);
    cudaFuncSetAttribute(gemm_mma_kernel<false>,
                         cudaFuncAttributeMaxDynamicSharedMemorySize, GSMEM_BYTES);
    cudaFuncSetAttribute(attn_mma_kernel,
                         cudaFuncAttributeMaxDynamicSharedMemorySize, ATT_SMEM_BYTES);

    // 1) QKV projection (output tf32-rounded for attention)
    {
        dim3 grid(3 * D_ / 128, M / 128);
        gemm_mma_kernel<true><<<grid, 256, GSMEM_BYTES>>>(xr, wqr, b_qkv, qkv,
                                                          M, 3 * D_, D_);
    }
    // 2) attention (output tf32-rounded for GEMM-2)
    {
        dim3 grid(T_ / 128, B_ * H_);
        attn_mma_kernel<<<grid, 256, ATT_SMEM_BYTES>>>(qkv, mask, att);
    }
    // 3) output projection (exact fp32 output)
    {
        dim3 grid(D_ / 128, M / 128);
        gemm_mma_kernel<false><<<grid, 256, GSMEM_BYTES>>>(att, wor, b_out, out,
                                                           M, D_, D_);
    }
}

// round 6
// speedup vs baseline: 7.5325x; 2.0303x over previous
#include <cuda_runtime.h>
#include <cuda_fp16.h>
#include <math.h>
#include <cstdint>

// Problem dims (fixed)
#define B_  4
#define T_  2048
#define D_  1024
#define H_  16
#define DH_ 64
#define M_  (B_ * T_)

// fp16 scratch
__device__ __half g_xh [(size_t)M_ * D_];          // x fp16
__device__ __half g_wqt[(size_t)3 * D_ * D_];      // W_qkv^T fp16 [3D][D]
__device__ __half g_wot[(size_t)D_ * D_];          // W_out^T fp16 [D][D]
__device__ __half g_qh [(size_t)M_ * D_];          // Q (pre-scaled) fp16
__device__ __half g_kh [(size_t)M_ * D_];          // K fp16
__device__ __half g_vh [(size_t)M_ * D_];          // V fp16
__device__ __half g_kc [(size_t)M_ * D_];          // compacted K
__device__ __half g_vtc[(size_t)B_ * H_ * DH_ * T_]; // compacted V^T [b][h][d][i]
__device__ __half g_ath[(size_t)M_ * D_];          // attention out fp16
__device__ int    g_kidx[B_ * T_];
__device__ int    g_cnt[B_];

#define QSCALE (0.125f * 1.44269504088896f)   // 1/8 * log2(e), for ex2

// ---------------------------------------------------------------------------
// helpers
// ---------------------------------------------------------------------------
__device__ __forceinline__ uint32_t pack_h2(float a, float b) {
    __half2 h;
    h.x = __float2half_rn(a);
    h.y = __float2half_rn(b);
    return *(uint32_t*)&h;
}
__device__ __forceinline__ float ex2f(float x) {
    float r;
    asm("ex2.approx.f32 %0, %1;" : "=f"(r) : "f"(x));
    return r;
}
__device__ __forceinline__ void mma16(float* d, const uint32_t* a,
                                      uint32_t b0, uint32_t b1) {
    asm volatile(
        "mma.sync.aligned.m16n8k16.row.col.f32.f16.f16.f32 "
        "{%0,%1,%2,%3}, {%4,%5,%6,%7}, {%8,%9}, {%0,%1,%2,%3};"
        : "+f"(d[0]), "+f"(d[1]), "+f"(d[2]), "+f"(d[3])
        : "r"(a[0]), "r"(a[1]), "r"(a[2]), "r"(a[3]), "r"(b0), "r"(b1));
}
__device__ __forceinline__ void cp16(uint32_t dst, const void* src) {
    asm volatile("cp.async.cg.shared.global [%0], [%1], 16;" :: "r"(dst), "l"(src));
}
__device__ __forceinline__ uint32_t smem_u32(const void* p) {
    uint32_t a;
    asm("{ .reg .u64 t; cvta.to.shared.u64 t, %1; cvt.u32.u64 %0, t; }"
        : "=r"(a) : "l"(p));
    return a;
}

// ---------------------------------------------------------------------------
// x -> fp16 (float4 -> 4 halves)
// ---------------------------------------------------------------------------
__global__ void conv_half_kernel(const float4* __restrict__ src,
                                 uint2* __restrict__ dst, int n4)
{
    int i = blockIdx.x * blockDim.x + threadIdx.x;
    int stride = gridDim.x * blockDim.x;
    for (; i < n4; i += stride) {
        float4 v = src[i];
        uint2 o;
        o.x = pack_h2(v.x, v.y);
        o.y = pack_h2(v.z, v.w);
        dst[i] = o;
    }
}

// ---------------------------------------------------------------------------
// W [K][N] fp32 -> Wt [N][K] fp16 (tiled transpose)
// ---------------------------------------------------------------------------
__global__ void convT_w_kernel(const float* __restrict__ src,
                               __half* __restrict__ dst, int Kdim, int Ndim)
{
    __shared__ float tile[32][33];
    int c0 = blockIdx.x * 32, r0 = blockIdx.y * 32;
    int x = threadIdx.x, y = threadIdx.y;   // 32 x 8
#pragma unroll
    for (int i = 0; i < 32; i += 8)
        tile[y + i][x] = src[(size_t)(r0 + y + i) * Ndim + c0 + x];
    __syncthreads();
#pragma unroll
    for (int i = 0; i < 32; i += 8)
        dst[(size_t)(c0 + y + i) * Kdim + r0 + x] =
            __float2half_rn(tile[x][y + i]);
}

// ---------------------------------------------------------------------------
// mask prefix-scan per batch: kidx (stable ascending) + cnt
// ---------------------------------------------------------------------------
__global__ void scan_mask_kernel(const int* __restrict__ mask,
                                 int* __restrict__ kidx, int* __restrict__ cnt)
{
    __shared__ int sums[256];
    const int b = blockIdx.x, t = threadIdx.x;
    const int* mb = mask + b * T_;
    int loc[8], c = 0;
#pragma unroll
    for (int j = 0; j < 8; j++) {
        loc[j] = mb[t * 8 + j];
        c += (loc[j] != 0);
    }
    sums[t] = c;
    __syncthreads();
    for (int off = 1; off < 256; off <<= 1) {
        int v = (t >= off) ? sums[t - off] : 0;
        __syncthreads();
        sums[t] += v;
        __syncthreads();
    }
    int pos = sums[t] - c;
#pragma unroll
    for (int j = 0; j < 8; j++)
        if (loc[j] != 0) kidx[b * T_ + pos++] = t * 8 + j;
    if (t == 255) cnt[b] = sums[255];
}

// ---------------------------------------------------------------------------
// Gather compacted K rows (all heads); pad rows zeroed
// ---------------------------------------------------------------------------
__global__ void gather_k_kernel()
{
    const int b = blockIdx.y, i0 = blockIdx.x * 64;
    const int cnt = g_cnt[b];
    const int padN = (cnt + 63) & ~63;
    if (i0 >= padN) return;
    const int tid = threadIdx.x;
    for (int task = tid; task < 64 * 128; task += 256) {
        int row = task >> 7, ch = task & 127;
        int i = i0 + row;
        uint4 v = make_uint4(0, 0, 0, 0);
        if (i < cnt) {
            int src = g_kidx[b * T_ + i];
            v = *(const uint4*)(g_kh + ((size_t)(b * T_ + src)) * D_ + ch * 8);
        }
        *(uint4*)(g_kc + ((size_t)(b * T_ + i)) * D_ + ch * 8) = v;
    }
}

// ---------------------------------------------------------------------------
// Gather compacted V^T: Vtc[b][h][d][i]; pad zeroed (NaN-safe for PV)
// ---------------------------------------------------------------------------
__global__ void gather_vt_kernel()
{
    __shared__ __half sm[64][72];
    const int i0 = blockIdx.x * 64, h = blockIdx.y, b = blockIdx.z;
    const int cnt = g_cnt[b];
    const int padN = (cnt + 63) & ~63;
    if (i0 >= padN) return;
    const int tid = threadIdx.x;
#pragma unroll
    for (int p = 0; p < 2; p++) {
        int task = tid + p * 256;
        int row = task >> 3, ch = task & 7;
        uint4 v = make_uint4(0, 0, 0, 0);
        if (i0 + row < cnt) {
            int src = g_kidx[b * T_ + i0 + row];
            v = *(const uint4*)(g_vh + ((size_t)(b * T_ + src)) * D_ +
                                h * DH_ + ch * 8);
        }
        *(uint4*)(&sm[row][ch * 8]) = v;
    }
    __syncthreads();
#pragma unroll
    for (int p = 0; p < 8; p++) {
        int task = tid + p * 256;
        int d = task >> 5, pr = task & 31;
        __half2 h2;
        h2.x = sm[2 * pr][d];
        h2.y = sm[2 * pr + 1][d];
        *(uint32_t*)(g_vtc + (((size_t)(b * H_ + h) * DH_ + d) * T_ +
                              i0 + 2 * pr)) = *(uint32_t*)&h2;
    }
}

// ---------------------------------------------------------------------------
// fp16 GEMM via mma.sync m16n8k16:
//   C[M,1024or3072] = A[M,1024] @ Wt[N][1024]^T + bias
// 128x128 tile, BK=32 halves, 8 warps (2x4, 64x32 each), 4-stage cp.async.
// MODE 0: fp32 out + bias.  MODE 1: split q/k/v fp16 out + bias (+Q scale).
// ---------------------------------------------------------------------------
#define GSTRIDE_H 40                       // halves per smem row (80B)
#define GSTAGE_B  (128 * GSTRIDE_H * 2 * 2)  // A + B = 20480 bytes
#define GSTAGES   4
#define GSMEM_B   (GSTAGES * GSTAGE_B)     // 81920

template <int MODE>
__global__ __launch_bounds__(256, 2)
void gemm_h_kernel(const __half* __restrict__ A, const __half* __restrict__ Wt,
                   const float* __restrict__ bias, float* __restrict__ outF,
                   __half* __restrict__ oq, __half* __restrict__ ok,
                   __half* __restrict__ ov)
{
    extern __shared__ char smc[];
    const uint32_t sb = smem_u32(smc);
    const int tid = threadIdx.x;
    const int w = tid >> 5, lane = tid & 31;
    const int g = lane >> 2, t = lane & 3;
    const int bn = blockIdx.x, bm = blockIdx.y;
    const int m0 = (w >> 2) * 64, n0 = (w & 3) * 32;

    const __half* Ag = A  + (size_t)bm * 128 * D_;
    const __half* Bg = Wt + (size_t)bn * 128 * D_;

    float acc[4][4][4];
#pragma unroll
    for (int mi = 0; mi < 4; mi++)
#pragma unroll
        for (int ni = 0; ni < 4; ni++)
#pragma unroll
            for (int j = 0; j < 4; j++) acc[mi][ni][j] = 0.f;

#define GH_LOAD(ch, s) do {                                                    \
        uint32_t abase = sb + (uint32_t)(s) * GSTAGE_B;                        \
        uint32_t bbase = abase + 128 * GSTRIDE_H * 2;                          \
        int k0 = (ch) * 32;                                                    \
        _Pragma("unroll")                                                      \
        for (int i = 0; i < 2; i++) {                                          \
            int task = tid + i * 256;                                          \
            int r = task >> 2, c = task & 3;                                   \
            cp16(abase + (uint32_t)(r * 80 + c * 16),                          \
                 Ag + (size_t)r * D_ + k0 + c * 8);                            \
            cp16(bbase + (uint32_t)(r * 80 + c * 16),                          \
                 Bg + (size_t)r * D_ + k0 + c * 8);                            \
        }                                                                      \
        asm volatile("cp.async.commit_group;" ::: "memory");                   \
    } while (0)

    const int NC = D_ / 32;   // 32 chunks
#pragma unroll
    for (int c = 0; c < GSTAGES; c++) GH_LOAD(c, c);

    for (int c = 0; c < NC; c++) {
        int s = c & (GSTAGES - 1);
        asm volatile("cp.async.wait_group 3;" ::: "memory");
        __syncthreads();
        const uint32_t* As = (const uint32_t*)(smc + (size_t)s * GSTAGE_B);
        const uint32_t* Bs = As + 128 * (GSTRIDE_H / 2);

#pragma unroll
        for (int ks = 0; ks < 2; ks++) {
            uint32_t af[4][4];
#pragma unroll
            for (int mi = 0; mi < 4; mi++) {
                int row = m0 + mi * 16 + g;
                af[mi][0] = As[row * 20 + ks * 8 + t];
                af[mi][1] = As[(row + 8) * 20 + ks * 8 + t];
                af[mi][2] = As[row * 20 + ks * 8 + t + 4];
                af[mi][3] = As[(row + 8) * 20 + ks * 8 + t + 4];
            }
#pragma unroll
            for (int ni = 0; ni < 4; ni++) {
                int brow = n0 + ni * 8 + g;
                uint32_t b0 = Bs[brow * 20 + ks * 8 + t];
                uint32_t b1 = Bs[brow * 20 + ks * 8 + t + 4];
#pragma unroll
                for (int mi = 0; mi < 4; mi++)
                    mma16(acc[mi][ni], af[mi], b0, b1);
            }
        }
        __syncthreads();
        if (c + GSTAGES < NC) {
            GH_LOAD(c + GSTAGES, s);
        } else {
            asm volatile("cp.async.commit_group;" ::: "memory");
        }
    }

    if (MODE == 0) {
#pragma unroll
        for (int mi = 0; mi < 4; mi++) {
            int rA = bm * 128 + m0 + mi * 16 + g;
            int rB = rA + 8;
#pragma unroll
            for (int ni = 0; ni < 4; ni++) {
                int col = bn * 128 + n0 + ni * 8 + t * 2;
                float bx = bias[col], by = bias[col + 1];
                *(float2*)(outF + (size_t)rA * D_ + col) =
                    make_float2(acc[mi][ni][0] + bx, acc[mi][ni][1] + by);
                *(float2*)(outF + (size_t)rB * D_ + col) =
                    make_float2(acc[mi][ni][2] + bx, acc[mi][ni][3] + by);
            }
        }
    } else {
        const int region = bn >> 3;             // 0=Q 1=K 2=V
        const int colbase = (bn & 7) * 128;
        __half* buf = (region == 0) ? oq : (region == 1) ? ok : ov;
        const float sc = (region == 0) ? QSCALE : 1.0f;
#pragma unroll
        for (int mi = 0; mi < 4; mi++) {
            int rA = bm * 128 + m0 + mi * 16 + g;
            int rB = rA + 8;
#pragma unroll
            for (int ni = 0; ni < 4; ni++) {
                int col = colbase + n0 + ni * 8 + t * 2;
                float bx = bias[region * D_ + col];
                float by = bias[region * D_ + col + 1];
                *(uint32_t*)(buf + (size_t)rA * D_ + col) =
                    pack_h2((acc[mi][ni][0] + bx) * sc,
                            (acc[mi][ni][1] + by) * sc);
                *(uint32_t*)(buf + (size_t)rB * D_ + col) =
                    pack_h2((acc[mi][ni][2] + bx) * sc,
                            (acc[mi][ni][3] + by) * sc);
            }
        }
    }
}

// ---------------------------------------------------------------------------
// fp16 flash attention over COMPACTED keys.
// Block: 128 q-rows x one (b,h); 8 warps x 16 q-rows. Tiles of 64 keys.
// Q pre-scaled by 0.125*log2e -> softmax uses ex2. Double-buffered cp.async.
// smem (bytes): Q 18432 | K 2x9216 | Vt 2x9216 | Pt 18432  = 73728
// ---------------------------------------------------------------------------
#define AQ_OFF   0
#define AK_OFF(s) (18432 + (s) * 9216)
#define AV_OFF(s) (36864 + (s) * 9216)
#define AP_OFF   55296
#define ATT_SMEM 73728

__global__ __launch_bounds__(256, 2)
void attn_h_kernel(const int* __restrict__ cntp, float dummy)
{
    extern __shared__ char smc[];
    const uint32_t sb = smem_u32(smc);
    uint32_t* Ptu = (uint32_t*)(smc + AP_OFF);
    const uint32_t* Qsu = (const uint32_t*)(smc + AQ_OFF);

    const int qb = blockIdx.x;
    const int bh = blockIdx.y;
    const int b  = bh >> 4;
    const int h  = bh & 15;
    const int tid = threadIdx.x;
    const int w = tid >> 5, lane = tid & 31;
    const int g = lane >> 2, t = lane & 3;
    const int w16 = w * 16;

    const int cnt = cntp[b];
    const int NT = (cnt + 63) >> 6;

    const __half* qbase = g_qh + ((size_t)(b * T_ + qb * 128)) * D_ + h * DH_;
    const __half* kcb   = g_kc + ((size_t)b * T_) * D_ + h * DH_;
    const __half* vtb   = g_vtc + ((size_t)(b * H_ + h) * DH_) * T_;

#define ATT_LOAD(kb, s) do {                                                   \
        uint32_t kdst = sb + AK_OFF(s);                                        \
        uint32_t vdst = sb + AV_OFF(s);                                        \
        int i0 = (kb) * 64;                                                    \
        _Pragma("unroll")                                                      \
        for (int i = 0; i < 2; i++) {                                          \
            int task = tid + i * 256;                                          \
            int row = task >> 3, ch = task & 7;                                \
            cp16(kdst + (uint32_t)(row * 144 + ch * 16),                       \
                 kcb + (size_t)(i0 + row) * D_ + ch * 8);                      \
            cp16(vdst + (uint32_t)(row * 144 + ch * 16),                       \
                 vtb + (size_t)row * T_ + i0 + ch * 8);                        \
        }                                                                      \
        asm volatile("cp.async.commit_group;" ::: "memory");                   \
    } while (0)

    if (NT > 0) ATT_LOAD(0, 0);
    // stage Q
#pragma unroll
    for (int i = 0; i < 4; i++) {
        int task = tid + i * 256;
        int row = task >> 3, ch = task & 7;
        cp16(sb + AQ_OFF + (uint32_t)(row * 144 + ch * 16),
             qbase + (size_t)row * D_ + ch * 8);
    }
    asm volatile("cp.async.commit_group;" ::: "memory");
    asm volatile("cp.async.wait_group 0;" ::: "memory");
    __syncthreads();

    uint32_t qf[4][4];
#pragma unroll
    for (int ks = 0; ks < 4; ks++) {
        int row = w16 + g;
        qf[ks][0] = Qsu[row * 36 + ks * 8 + t];
        qf[ks][1] = Qsu[(row + 8) * 36 + ks * 8 + t];
        qf[ks][2] = Qsu[row * 36 + ks * 8 + t + 4];
        qf[ks][3] = Qsu[(row + 8) * 36 + ks * 8 + t + 4];
    }

    float of[8][4];
#pragma unroll
    for (int n = 0; n < 8; n++)
#pragma unroll
        for (int j = 0; j < 4; j++) of[n][j] = 0.f;
    float mrA = -1.0e30f, mrB = -1.0e30f, lrA = 0.f, lrB = 0.f;

    for (int kb = 0; kb < NT; kb++) {
        int s = kb & 1;
        __syncthreads();
        if (kb + 1 < NT) {
            ATT_LOAD(kb + 1, s ^ 1);
        } else {
            asm volatile("cp.async.commit_group;" ::: "memory");
        }
        asm volatile("cp.async.wait_group 1;" ::: "memory");
        __syncthreads();

        const uint32_t* Ksu = (const uint32_t*)(smc + AK_OFF(s));
        const uint32_t* Vsu = (const uint32_t*)(smc + AV_OFF(s));

        // ---- S = Q K^T ----
        float sf[8][4];
#pragma unroll
        for (int n = 0; n < 8; n++)
#pragma unroll
            for (int j = 0; j < 4; j++) sf[n][j] = 0.f;
#pragma unroll
        for (int ks = 0; ks < 4; ks++) {
#pragma unroll
            for (int n = 0; n < 8; n++) {
                uint32_t b0 = Ksu[(n * 8 + g) * 36 + ks * 8 + t];
                uint32_t b1 = Ksu[(n * 8 + g) * 36 + ks * 8 + t + 4];
                mma16(sf[n], qf[ks], b0, b1);
            }
        }

        // ---- validity (tail pad) + online softmax (log2 domain) ----
        const int cbase = kb * 64;
#pragma unroll
        for (int n = 0; n < 8; n++) {
            int c0 = cbase + n * 8 + t * 2;
            if (c0 >= cnt)     { sf[n][0] = -1.0e5f; sf[n][2] = -1.0e5f; }
            if (c0 + 1 >= cnt) { sf[n][1] = -1.0e5f; sf[n][3] = -1.0e5f; }
        }
        float mA = -1.0e30f, mB = -1.0e30f;
#pragma unroll
        for (int n = 0; n < 8; n++) {
            mA = fmaxf(mA, fmaxf(sf[n][0], sf[n][1]));
            mB = fmaxf(mB, fmaxf(sf[n][2], sf[n][3]));
        }
        mA = fmaxf(mA, __shfl_xor_sync(0xffffffffu, mA, 1));
        mA = fmaxf(mA, __shfl_xor_sync(0xffffffffu, mA, 2));
        mB = fmaxf(mB, __shfl_xor_sync(0xffffffffu, mB, 1));
        mB = fmaxf(mB, __shfl_xor_sync(0xffffffffu, mB, 2));

        float mnA = fmaxf(mrA, mA), mnB = fmaxf(mrB, mB);
        float corrA = ex2f(mrA - mnA), corrB = ex2f(mrB - mnB);
        mrA = mnA; mrB = mnB;

        float psA = 0.f, psB = 0.f;
#pragma unroll
        for (int n = 0; n < 8; n++) {
            float p0 = ex2f(sf[n][0] - mnA);
            float p1 = ex2f(sf[n][1] - mnA);
            float p2 = ex2f(sf[n][2] - mnB);
            float p3 = ex2f(sf[n][3] - mnB);
            psA += p0 + p1; psB += p2 + p3;
            Ptu[(w16 + g) * 36 + n * 4 + t]     = pack_h2(p0, p1);
            Ptu[(w16 + g + 8) * 36 + n * 4 + t] = pack_h2(p2, p3);
        }
        psA += __shfl_xor_sync(0xffffffffu, psA, 1);
        psA += __shfl_xor_sync(0xffffffffu, psA, 2);
        psB += __shfl_xor_sync(0xffffffffu, psB, 1);
        psB += __shfl_xor_sync(0xffffffffu, psB, 2);
        lrA = lrA * corrA + psA;
        lrB = lrB * corrB + psB;
#pragma unroll
        for (int n = 0; n < 8; n++) {
            of[n][0] *= corrA; of[n][1] *= corrA;
            of[n][2] *= corrB; of[n][3] *= corrB;
        }
        __syncwarp();   // warp-private Pt rows

        // ---- O += P V ----
#pragma unroll
        for (int ks = 0; ks < 4; ks++) {
            uint32_t pa[4];
            pa[0] = Ptu[(w16 + g) * 36 + ks * 8 + t];
            pa[1] = Ptu[(w16 + g + 8) * 36 + ks * 8 + t];
            pa[2] = Ptu[(w16 + g) * 36 + ks * 8 + t + 4];
            pa[3] = Ptu[(w16 + g + 8) * 36 + ks * 8 + t + 4];
#pragma unroll
            for (int n = 0; n < 8; n++) {
                uint32_t b0 = Vsu[(n * 8 + g) * 36 + ks * 8 + t];
                uint32_t b1 = Vsu[(n * 8 + g) * 36 + ks * 8 + t + 4];
                mma16(of[n], pa, b0, b1);
            }
        }
    }

    // ---- normalize + fp16 store ----
    float invA = 1.0f / lrA, invB = 1.0f / lrB;
    __half* ob = g_ath + ((size_t)(b * T_ + qb * 128)) * D_ + h * DH_;
#pragma unroll
    for (int n = 0; n < 8; n++) {
        int col = n * 8 + t * 2;
        *(uint32_t*)(ob + (size_t)(w16 + g) * D_ + col) =
            pack_h2(of[n][0] * invA, of[n][1] * invA);
        *(uint32_t*)(ob + (size_t)(w16 + g + 8) * D_ + col) =
            pack_h2(of[n][2] * invB, of[n][3] * invB);
    }
}

// ---------------------------------------------------------------------------
// launch
// ---------------------------------------------------------------------------
extern "C" void kernel_launch(void* const* d_in, const int* in_sizes, int n_in,
                              void* d_out, int out_size)
{
    const float* x     = (const float*)d_in[0];
    const int*   mask  = (const int*)  d_in[1];
    const float* W_qkv = (const float*)d_in[2];
    const float* b_qkv = (const float*)d_in[3];
    const float* W_out = (const float*)d_in[4];
    const float* b_out = (const float*)d_in[5];
    float* out = (float*)d_out;

    void* p;
    cudaGetSymbolAddress(&p, g_xh);   __half* xh  = (__half*)p;
    cudaGetSymbolAddress(&p, g_wqt);  __half* wqt = (__half*)p;
    cudaGetSymbolAddress(&p, g_wot);  __half* wot = (__half*)p;
    cudaGetSymbolAddress(&p, g_qh);   __half* qh  = (__half*)p;
    cudaGetSymbolAddress(&p, g_kh);   __half* kh  = (__half*)p;
    cudaGetSymbolAddress(&p, g_vh);   __half* vh  = (__half*)p;
    cudaGetSymbolAddress(&p, g_ath);  __half* ath = (__half*)p;
    cudaGetSymbolAddress(&p, g_kidx); int* kidx   = (int*)p;
    cudaGetSymbolAddress(&p, g_cnt);  int* cnt    = (int*)p;

    // 0) conversions (+ mask scan, independent)
    conv_half_kernel<<<1024, 256>>>((const float4*)x, (uint2*)xh, M_ * D_ / 4);
    {
        dim3 blk(32, 8);
        convT_w_kernel<<<dim3(3 * D_ / 32, D_ / 32), blk>>>(W_qkv, wqt, D_, 3 * D_);
        convT_w_kernel<<<dim3(D_ / 32, D_ / 32), blk>>>(W_out, wot, D_, D_);
    }
    scan_mask_kernel<<<B_, 256>>>(mask, kidx, cnt);

    cudaFuncSetAttribute(gemm_h_kernel<0>,
                         cudaFuncAttributeMaxDynamicSharedMemorySize, GSMEM_B);
    cudaFuncSetAttribute(gemm_h_kernel<1>,
                         cudaFuncAttributeMaxDynamicSharedMemorySize, GSMEM_B);
    cudaFuncSetAttribute(attn_h_kernel,
                         cudaFuncAttributeMaxDynamicSharedMemorySize, ATT_SMEM);

    // 1) QKV projection -> q(scaled)/k/v fp16
    {
        dim3 grid(3 * D_ / 128, M_ / 128);
        gemm_h_kernel<1><<<grid, 256, GSMEM_B>>>(xh, wqt, b_qkv, nullptr,
                                                 qh, kh, vh);
    }
    // 2) compaction gathers
    gather_k_kernel<<<dim3(T_ / 64, B_), 256>>>();
    gather_vt_kernel<<<dim3(T_ / 64, H_, B_), 256>>>();
    // 3) attention
    {
        dim3 grid(T_ / 128, B_ * H_);
        attn_h_kernel<<<grid, 256, ATT_SMEM>>>(cnt, 0.f);
    }
    // 4) output projection (fp32 + bias)
    {
        dim3 grid(D_ / 128, M_ / 128);
        gemm_h_kernel<0><<<grid, 256, GSMEM_B>>>(ath, wot, b_out, out,
                                                 nullptr, nullptr, nullptr);
    }
}